// round 9
// baseline (speedup 1.0000x reference)
#include <cuda_runtime.h>
#include <cstdint>

// ---------------- scratch (device globals) ----------------------------------
#define MAXN 50176   // padded 50000
#define MAXE 1048576
__device__ float g_h  [MAXN * 128];
__device__ float g_pool[256 * 128];
__device__ float g_cnt [256];
__device__ int   g_deg [MAXN];
__device__ int   g_off [MAXN];
__device__ int   g_cur [MAXN];
__device__ int   g_adj [MAXE];

// ---------------- zero -------------------------------------------------------
__global__ void zero_kernel(float* __restrict__ p, int n4) {
    int i = blockIdx.x * blockDim.x + threadIdx.x;
    if (i < n4) ((float4*)p)[i] = make_float4(0.f, 0.f, 0.f, 0.f);
}

// ---------------- CSR build --------------------------------------------------
__global__ void count_kernel(const int* __restrict__ dst, int* __restrict__ deg, int E) {
    int e = blockIdx.x * blockDim.x + threadIdx.x;
    if (e < E) atomicAdd(deg + __ldg(dst + e), 1);
}

__global__ void scan_kernel(const int* __restrict__ deg, int* __restrict__ off,
                            int* __restrict__ cur, int N) {
    __shared__ int part[1024];
    const int tid = threadIdx.x;
    const int seg = (N + 1023) / 1024;
    const int start = tid * seg;
    const int end = min(start + seg, N);
    int s = 0;
    for (int i = start; i < end; i++) s += deg[i];
    part[tid] = s;
    __syncthreads();
    int v = s;
#pragma unroll
    for (int d = 1; d < 1024; d <<= 1) {
        int t = (tid >= d) ? part[tid - d] : 0;
        __syncthreads();
        part[tid] += t;
        __syncthreads();
    }
    int run = part[tid] - v;
    for (int i = start; i < end; i++) {
        off[i] = run; cur[i] = run;
        run += deg[i];
    }
}

__global__ void fill_kernel(const int* __restrict__ src, const int* __restrict__ dst,
                            int* __restrict__ cur, int* __restrict__ adj, int E) {
    int e = blockIdx.x * blockDim.x + threadIdx.x;
    if (e < E) {
        int p = atomicAdd(cur + __ldg(dst + e), 1);
        adj[p] = __ldg(src + e);
    }
}

__global__ void cnt_kernel(const int* __restrict__ batch, float* __restrict__ cnt, int N) {
    int i = blockIdx.x * blockDim.x + threadIdx.x;
    if (i < N) atomicAdd(cnt + __ldg(batch + i), 1.0f);
}

// ---------------- persistent warp-specialized fused GIN layer ----------------
#define AS 132                 // Atile row stride (floats)
#define TROWS 192              // rows per tile (24 row-groups x 16 col-groups = 384 thr)
#define NSM 148
#define NCONS 384              // 12 consumer warps
#define SMEM_BYTES ((2 * TROWS * AS + 2 * 16 * 128) * 4)
#define CONS_BAR() asm volatile("bar.sync 1, 384;" ::: "memory")

__device__ __forceinline__ void stage_w(const float* __restrict__ W, float* __restrict__ Wsm,
                                        int k0, int tid) {
    for (int ch = tid; ch < 512; ch += NCONS) {
        int r = ch >> 5, c4 = ch & 31;
        const float* g = W + (size_t)(k0 + r) * 128 + c4 * 4;
        unsigned sm = (unsigned)__cvta_generic_to_shared(Wsm + r * 128 + c4 * 4);
        asm volatile("cp.async.cg.shared.global [%0], [%1], 16;" :: "r"(sm), "l"(g));
    }
    asm volatile("cp.async.commit_group;");
}

__device__ __forceinline__ void gather_rows(const float* __restrict__ X,
                                            const int* __restrict__ adj,
                                            const int* __restrict__ off,
                                            const int* __restrict__ deg,
                                            float* __restrict__ Abuf,
                                            int row0, int N, int warp, int nwarps, int lane) {
    for (int row = warp; row < TROWS; row += nwarps) {
        int node = row0 + row;
        float4 a0 = make_float4(0.f, 0.f, 0.f, 0.f);
        float4 a1 = a0, a2 = a0, a3 = a0;
        if (node < N) {
            a0 = __ldg(((const float4*)(X + (size_t)node * 128)) + lane);
            const int start = __ldg(off + node);
            const int d = __ldg(deg + node);
            int j = 0;
            for (; j + 4 <= d; j += 4) {
                int n0 = __ldg(adj + start + j);
                int n1 = __ldg(adj + start + j + 1);
                int n2 = __ldg(adj + start + j + 2);
                int n3 = __ldg(adj + start + j + 3);
                float4 v0 = __ldg(((const float4*)(X + (size_t)n0 * 128)) + lane);
                float4 v1 = __ldg(((const float4*)(X + (size_t)n1 * 128)) + lane);
                float4 v2 = __ldg(((const float4*)(X + (size_t)n2 * 128)) + lane);
                float4 v3 = __ldg(((const float4*)(X + (size_t)n3 * 128)) + lane);
                a0.x += v0.x; a0.y += v0.y; a0.z += v0.z; a0.w += v0.w;
                a1.x += v1.x; a1.y += v1.y; a1.z += v1.z; a1.w += v1.w;
                a2.x += v2.x; a2.y += v2.y; a2.z += v2.z; a2.w += v2.w;
                a3.x += v3.x; a3.y += v3.y; a3.z += v3.z; a3.w += v3.w;
            }
            for (; j < d; j++) {
                int n0 = __ldg(adj + start + j);
                float4 v0 = __ldg(((const float4*)(X + (size_t)n0 * 128)) + lane);
                a0.x += v0.x; a0.y += v0.y; a0.z += v0.z; a0.w += v0.w;
            }
            a0.x += a1.x + a2.x + a3.x;
            a0.y += a1.y + a2.y + a3.y;
            a0.z += a1.z + a2.z + a3.z;
            a0.w += a1.w + a2.w + a3.w;
        }
        *(float4*)&Abuf[row * AS + lane * 4] = a0;
    }
}

__device__ __forceinline__ void gemm_from_atile(const float* __restrict__ Atile,
                                                const float* __restrict__ W,
                                                float* __restrict__ Ws,
                                                int tid, int rrow, int ccol,
                                                unsigned long long acc[8][4]) {
    stage_w(W, Ws, 0, tid);
    for (int s = 0; s < 8; s++) {
        if (s < 7) {
            stage_w(W, Ws + ((s + 1) & 1) * 2048, (s + 1) * 16, tid);
            asm volatile("cp.async.wait_group 1;");
        } else {
            asm volatile("cp.async.wait_group 0;");
        }
        CONS_BAR();
        const float* Wb = Ws + (s & 1) * 2048;
#pragma unroll
        for (int k4l = 0; k4l < 4; k4l++) {
            const int kg = s * 16 + k4l * 4;
            float4 av[8];
#pragma unroll
            for (int i = 0; i < 8; i++)
                av[i] = *(const float4*)&Atile[(rrow + i) * AS + kg];
#pragma unroll
            for (int kk = 0; kk < 4; kk++) {
                const float* wrow = Wb + (k4l * 4 + kk) * 128 + ccol;
                ulonglong2 w01 = *(const ulonglong2*)wrow;
                ulonglong2 w23 = *(const ulonglong2*)(wrow + 4);
#pragma unroll
                for (int i = 0; i < 8; i++) {
                    float a = (kk == 0) ? av[i].x : (kk == 1) ? av[i].y
                            : (kk == 2) ? av[i].z : av[i].w;
                    unsigned long long a2;
                    asm("mov.b64 %0, {%1, %1};" : "=l"(a2) : "f"(a));
                    asm("fma.rn.f32x2 %0, %1, %2, %0;" : "+l"(acc[i][0]) : "l"(a2), "l"(w01.x));
                    asm("fma.rn.f32x2 %0, %1, %2, %0;" : "+l"(acc[i][1]) : "l"(a2), "l"(w01.y));
                    asm("fma.rn.f32x2 %0, %1, %2, %0;" : "+l"(acc[i][2]) : "l"(a2), "l"(w23.x));
                    asm("fma.rn.f32x2 %0, %1, %2, %0;" : "+l"(acc[i][3]) : "l"(a2), "l"(w23.y));
                }
            }
        }
        CONS_BAR();
    }
}

__device__ __forceinline__ void consumer_tile(float* __restrict__ Atile,
                                              float* __restrict__ Ws,
                                              const float* __restrict__ Wa, const float* __restrict__ ba,
                                              const float* __restrict__ Wb, const float* __restrict__ bbv,
                                              float* __restrict__ OUT,
                                              const int* __restrict__ batch, float* __restrict__ pool,
                                              int row0, int N, int mode,
                                              int tid, int rrow, int ccol) {
    unsigned long long acc[8][4];
#pragma unroll
    for (int i = 0; i < 8; i++)
#pragma unroll
        for (int j = 0; j < 4; j++) acc[i][j] = 0ull;

    gemm_from_atile(Atile, Wa, Ws, tid, rrow, ccol, acc);

    {   // epilogue1: relu+bias -> Atile
        float4 bv0 = __ldg((const float4*)(ba + ccol));
        float4 bv1 = __ldg((const float4*)(ba + ccol + 4));
        float bb[8] = {bv0.x, bv0.y, bv0.z, bv0.w, bv1.x, bv1.y, bv1.z, bv1.w};
#pragma unroll
        for (int i = 0; i < 8; i++) {
            float o[8];
#pragma unroll
            for (int j = 0; j < 4; j++) {
                float lo, hi;
                asm("mov.b64 {%0, %1}, %2;" : "=f"(lo), "=f"(hi) : "l"(acc[i][j]));
                o[2 * j]     = fmaxf(lo + bb[2 * j], 0.f);
                o[2 * j + 1] = fmaxf(hi + bb[2 * j + 1], 0.f);
                acc[i][j] = 0ull;
            }
            *(float4*)&Atile[(rrow + i) * AS + ccol]     = make_float4(o[0], o[1], o[2], o[3]);
            *(float4*)&Atile[(rrow + i) * AS + ccol + 4] = make_float4(o[4], o[5], o[6], o[7]);
        }
    }
    CONS_BAR();

    gemm_from_atile(Atile, Wb, Ws, tid, rrow, ccol, acc);

    {   // epilogue2
        float4 bv0 = __ldg((const float4*)(bbv + ccol));
        float4 bv1 = __ldg((const float4*)(bbv + ccol + 4));
        float bb[8] = {bv0.x, bv0.y, bv0.z, bv0.w, bv1.x, bv1.y, bv1.z, bv1.w};
#pragma unroll
        for (int i = 0; i < 8; i++) {
            int grow = row0 + rrow + i;
            if (grow < N) {
                float o[8];
#pragma unroll
                for (int j = 0; j < 4; j++) {
                    float lo, hi;
                    asm("mov.b64 {%0, %1}, %2;" : "=f"(lo), "=f"(hi) : "l"(acc[i][j]));
                    o[2 * j]     = lo + bb[2 * j];
                    o[2 * j + 1] = hi + bb[2 * j + 1];
                }
                if (mode == 0) {
                    *(float4*)(OUT + (size_t)grow * 128 + ccol)     = make_float4(o[0], o[1], o[2], o[3]);
                    *(float4*)(OUT + (size_t)grow * 128 + ccol + 4) = make_float4(o[4], o[5], o[6], o[7]);
                } else {
                    int g = __ldg(batch + grow);
                    float* p = pool + (size_t)g * 128 + ccol;
                    asm volatile("red.global.add.v4.f32 [%0], {%1, %2, %3, %4};"
                                 :: "l"(p), "f"(o[0]), "f"(o[1]), "f"(o[2]), "f"(o[3]) : "memory");
                    asm volatile("red.global.add.v4.f32 [%0], {%1, %2, %3, %4};"
                                 :: "l"(p + 4), "f"(o[4]), "f"(o[5]), "f"(o[6]), "f"(o[7]) : "memory");
                }
            }
        }
    }
}

__global__ __launch_bounds__(512, 1)
void fused_layer_kernel(const float* __restrict__ X,
                        const int* __restrict__ adj, const int* __restrict__ off,
                        const int* __restrict__ deg,
                        const float* __restrict__ Wa, const float* __restrict__ ba,
                        const float* __restrict__ Wb, const float* __restrict__ bbv,
                        float* __restrict__ OUT,
                        const int* __restrict__ batch, float* __restrict__ pool,
                        int N, int mode) {
    extern __shared__ float sm[];
    float* Abuf0 = sm;
    float* Abuf1 = sm + TROWS * AS;
    float* Ws    = sm + 2 * TROWS * AS;

    const int tid = threadIdx.x, wid = tid >> 5, lane = tid & 31;
    const int bid = blockIdx.x;
    const int ntiles = (N + TROWS - 1) / TROWS;
    const int nt = (ntiles - bid + NSM - 1) / NSM;
    if (nt <= 0) return;

    // consumer geometry (tid 0..383): 24 row-groups x 16 col-groups
    const int tx = tid & 15, ty = tid >> 4;
    const int rrow = ty * 8, ccol = tx * 8;

    // prologue: all 16 warps gather tile 0
    gather_rows(X, adj, off, deg, Abuf0, bid * TROWS, N, wid, 16, lane);
    __syncthreads();

    for (int i = 0; i < nt; i++) {
        float* Ab = (i & 1) ? Abuf1 : Abuf0;
        int row0 = (bid + i * NSM) * TROWS;
        if (tid < NCONS) {
            consumer_tile(Ab, Ws, Wa, ba, Wb, bbv, OUT, batch, pool,
                          row0, N, mode, tid, rrow, ccol);
        } else {
            if (i + 1 < nt) {
                float* An = (i & 1) ? Abuf0 : Abuf1;
                gather_rows(X, adj, off, deg, An, (bid + (i + 1) * NSM) * TROWS,
                            N, wid - 12, 4, lane);
            }
        }
        __syncthreads();
    }
}

// ---------------- head: out = (sums/cnt) @ Wl + bl --------------------------
__global__ void final_kernel(const float* __restrict__ sums, const float* __restrict__ cnt,
                             const float* __restrict__ Wl, const float* __restrict__ bl,
                             float* __restrict__ out) {
    int g = blockIdx.x;
    int o = threadIdx.x;  // 64 threads
    __shared__ float p[128];
    float c = fmaxf(__ldg(cnt + g), 1.0f);
    for (int k = threadIdx.x; k < 128; k += 64)
        p[k] = __ldg(sums + g * 128 + k) / c;
    __syncthreads();
    float acc = __ldg(bl + o);
#pragma unroll 16
    for (int k = 0; k < 128; k++)
        acc += p[k] * __ldg(Wl + k * 64 + o);
    out[g * 64 + o] = acc;
}

// ---------------- launch -----------------------------------------------------
extern "C" void kernel_launch(void* const* d_in, const int* in_sizes, int n_in,
                              void* d_out, int out_size) {
    const float* x     = (const float*)d_in[0];
    const int*   ei    = (const int*)  d_in[1];
    const int*   batch = (const int*)  d_in[2];
    const float* W1a = (const float*)d_in[3];
    const float* b1a = (const float*)d_in[4];
    const float* W1b = (const float*)d_in[5];
    const float* b1b = (const float*)d_in[6];
    const float* W2a = (const float*)d_in[7];
    const float* b2a = (const float*)d_in[8];
    const float* W2b = (const float*)d_in[9];
    const float* b2b = (const float*)d_in[10];
    const float* Wl  = (const float*)d_in[11];
    const float* bl  = (const float*)d_in[12];
    float* out = (float*)d_out;

    const int N = in_sizes[0] / 128;
    const int E = in_sizes[1] / 2;
    const int* src = ei;
    const int* dst = ei + E;

    float *h, *pool, *cnt;
    int *deg, *off, *cur, *adj;
    cudaGetSymbolAddress((void**)&h,    g_h);
    cudaGetSymbolAddress((void**)&pool, g_pool);
    cudaGetSymbolAddress((void**)&cnt,  g_cnt);
    cudaGetSymbolAddress((void**)&deg,  g_deg);
    cudaGetSymbolAddress((void**)&off,  g_off);
    cudaGetSymbolAddress((void**)&cur,  g_cur);
    cudaGetSymbolAddress((void**)&adj,  g_adj);

    cudaFuncSetAttribute(fused_layer_kernel,
                         cudaFuncAttributeMaxDynamicSharedMemorySize, SMEM_BYTES);

    const int eblocks = (E + 255) / 256;
    const int nblocks = (N + 255) / 256;

    // ---- CSR build (once per launch) ----
    zero_kernel <<<(MAXN / 4 + 255) / 256, 256>>>((float*)deg, MAXN / 4);
    count_kernel<<<eblocks, 256>>>(dst, deg, E);
    scan_kernel <<<1, 1024>>>(deg, off, cur, N);
    fill_kernel <<<eblocks, 256>>>(src, dst, cur, adj, E);

    // ---- pool init + counts ----
    zero_kernel<<<32, 256>>>(pool, 256 * 128 / 4);
    zero_kernel<<<1,  64>>>(cnt, 64);
    cnt_kernel <<<nblocks, 256>>>(batch, cnt, N);

    // ---- layer 1: h = MLP1(x + gather) ----
    fused_layer_kernel<<<NSM, 512, SMEM_BYTES>>>(
        x, adj, off, deg, W1a, b1a, W1b, b1b, h, batch, pool, N, 0);

    // ---- layer 2: pool += MLP2(h + gather), fused ----
    fused_layer_kernel<<<NSM, 512, SMEM_BYTES>>>(
        h, adj, off, deg, W2a, b2a, W2b, b2b, nullptr, batch, pool, N, 1);

    // ---- head ----
    final_kernel<<<256, 64>>>(pool, cnt, Wl, bl, out);
}

// round 10
// speedup vs baseline: 1.0572x; 1.0572x over previous
#include <cuda_runtime.h>
#include <cstdint>

// ---------------- scratch (device globals) ----------------------------------
#define MAXN 50176   // padded 50000
#define MAXE 1048576
__device__ float g_y  [MAXN * 128];
__device__ float g_h  [MAXN * 128];
__device__ float g_pool[256 * 128];
__device__ float g_cnt [256];
__device__ int   g_deg [MAXN];
__device__ int   g_off [MAXN];
__device__ int   g_cur [MAXN];
__device__ int   g_adj [MAXE];

// ---------------- zero -------------------------------------------------------
__global__ void zero_kernel(float* __restrict__ p, int n4) {
    int i = blockIdx.x * blockDim.x + threadIdx.x;
    if (i < n4) ((float4*)p)[i] = make_float4(0.f, 0.f, 0.f, 0.f);
}

// ---------------- CSR build --------------------------------------------------
__global__ void count_kernel(const int* __restrict__ dst, int* __restrict__ deg, int E) {
    int e = blockIdx.x * blockDim.x + threadIdx.x;
    if (e < E) atomicAdd(deg + __ldg(dst + e), 1);
}

__global__ void scan_kernel(const int* __restrict__ deg, int* __restrict__ off,
                            int* __restrict__ cur, int N) {
    __shared__ int part[1024];
    const int tid = threadIdx.x;
    const int seg = (N + 1023) / 1024;
    const int start = tid * seg;
    const int end = min(start + seg, N);
    int s = 0;
    for (int i = start; i < end; i++) s += deg[i];
    part[tid] = s;
    __syncthreads();
    int v = s;
#pragma unroll
    for (int d = 1; d < 1024; d <<= 1) {
        int t = (tid >= d) ? part[tid - d] : 0;
        __syncthreads();
        part[tid] += t;
        __syncthreads();
    }
    int run = part[tid] - v;
    for (int i = start; i < end; i++) {
        off[i] = run; cur[i] = run;
        run += deg[i];
    }
}

__global__ void fill_kernel(const int* __restrict__ src, const int* __restrict__ dst,
                            int* __restrict__ cur, int* __restrict__ adj, int E) {
    int e = blockIdx.x * blockDim.x + threadIdx.x;
    if (e < E) {
        int p = atomicAdd(cur + __ldg(dst + e), 1);
        adj[p] = __ldg(src + e);
    }
}

__global__ void cnt_kernel(const int* __restrict__ batch, float* __restrict__ cnt, int N) {
    int i = blockIdx.x * blockDim.x + threadIdx.x;
    if (i < N) atomicAdd(cnt + __ldg(batch + i), 1.0f);
}

// ---------------- standalone SGEMM (f32x2), guarded A loads, no/opt bias -----
#define TK 16

__global__ __launch_bounds__(256, 2)
void gemm128_kernel(const float* __restrict__ A, const float* __restrict__ W,
                    float* __restrict__ C, int M) {
    __shared__ float As[2][128][TK];
    __shared__ float Ws[2][TK][128];
    const int tid  = threadIdx.x;
    const int row0 = blockIdx.x * 128;
    const int tx = tid & 15, ty = tid >> 4;
    const int rrow = ty * 8, ccol = tx * 8;

    unsigned long long acc[8][4];
#pragma unroll
    for (int i = 0; i < 8; i++)
#pragma unroll
        for (int j = 0; j < 4; j++) acc[i][j] = 0ull;

#define STAGE(K0, BUF) do {                                                     \
        _Pragma("unroll")                                                       \
        for (int t = 0; t < 2; t++) {                                           \
            int ch = tid + t * 256;                                             \
            int r = ch >> 2, c = ch & 3;                                        \
            int grow = row0 + r;                                                \
            int sz = (grow < M) ? 16 : 0;                                       \
            const float* g = A + (size_t)grow * 128 + (K0) + c * 4;             \
            unsigned sm = (unsigned)__cvta_generic_to_shared(&As[BUF][r][c*4]); \
            asm volatile("cp.async.cg.shared.global [%0], [%1], 16, %2;"        \
                         :: "r"(sm), "l"(g), "r"(sz));                          \
        }                                                                       \
        _Pragma("unroll")                                                       \
        for (int t = 0; t < 2; t++) {                                           \
            int ch = tid + t * 256;                                             \
            int r = ch >> 5, c = ch & 31;                                       \
            const float* g = W + (size_t)((K0) + r) * 128 + c * 4;              \
            unsigned sm = (unsigned)__cvta_generic_to_shared(&Ws[BUF][r][c*4]); \
            asm volatile("cp.async.cg.shared.global [%0], [%1], 16;"            \
                         :: "r"(sm), "l"(g));                                   \
        }                                                                       \
        asm volatile("cp.async.commit_group;");                                 \
    } while (0)

    STAGE(0, 0);

    for (int s = 0; s < 128 / TK; s++) {
        if (s < 128 / TK - 1) {
            STAGE((s + 1) * TK, (s + 1) & 1);
            asm volatile("cp.async.wait_group 1;");
        } else {
            asm volatile("cp.async.wait_group 0;");
        }
        __syncthreads();

        const int b = s & 1;
#pragma unroll
        for (int k4 = 0; k4 < TK / 4; k4++) {
            float4 av[8];
#pragma unroll
            for (int i = 0; i < 8; i++)
                av[i] = *(const float4*)&As[b][rrow + i][k4 * 4];
#pragma unroll
            for (int kk = 0; kk < 4; kk++) {
                int k = k4 * 4 + kk;
                ulonglong2 w01 = *(const ulonglong2*)&Ws[b][k][ccol];
                ulonglong2 w23 = *(const ulonglong2*)&Ws[b][k][ccol + 4];
#pragma unroll
                for (int i = 0; i < 8; i++) {
                    float a = (kk == 0) ? av[i].x : (kk == 1) ? av[i].y
                            : (kk == 2) ? av[i].z : av[i].w;
                    unsigned long long a2;
                    asm("mov.b64 %0, {%1, %1};" : "=l"(a2) : "f"(a));
                    asm("fma.rn.f32x2 %0, %1, %2, %0;" : "+l"(acc[i][0]) : "l"(a2), "l"(w01.x));
                    asm("fma.rn.f32x2 %0, %1, %2, %0;" : "+l"(acc[i][1]) : "l"(a2), "l"(w01.y));
                    asm("fma.rn.f32x2 %0, %1, %2, %0;" : "+l"(acc[i][2]) : "l"(a2), "l"(w23.x));
                    asm("fma.rn.f32x2 %0, %1, %2, %0;" : "+l"(acc[i][3]) : "l"(a2), "l"(w23.y));
                }
            }
        }
        __syncthreads();
    }

    // epilogue: raw store (no bias/relu — bias applied downstream in gather)
#pragma unroll
    for (int i = 0; i < 8; i++) {
        int grow = row0 + rrow + i;
        if (grow < M) {
            float o[8];
#pragma unroll
            for (int j = 0; j < 4; j++) {
                float lo, hi;
                asm("mov.b64 {%0, %1}, %2;" : "=f"(lo), "=f"(hi) : "l"(acc[i][j]));
                o[2 * j] = lo; o[2 * j + 1] = hi;
            }
            *(float4*)(C + (size_t)grow * 128 + ccol)     = make_float4(o[0], o[1], o[2], o[3]);
            *(float4*)(C + (size_t)grow * 128 + ccol + 4) = make_float4(o[4], o[5], o[6], o[7]);
        }
    }
}

// ---------------- persistent warp-specialized gather + single GEMM -----------
// Producers: Atile[row] = relu(Y[node] + sum_j Y[adj] + bg). Consumers: @W + bw.
#define AS 132
#define NSM 148
#define SMEM_BYTES ((2 * 128 * AS + 2 * 16 * 128) * 4)
#define CONS_BAR() asm volatile("bar.sync 1, 256;" ::: "memory")

__device__ __forceinline__ void stage_w(const float* __restrict__ W, float* __restrict__ Wsm,
                                        int k0, int tid) {
#pragma unroll
    for (int t = 0; t < 2; t++) {
        int ch = tid + t * 256;
        int r = ch >> 5, c4 = ch & 31;
        const float* g = W + (size_t)(k0 + r) * 128 + c4 * 4;
        unsigned sm = (unsigned)__cvta_generic_to_shared(Wsm + r * 128 + c4 * 4);
        asm volatile("cp.async.cg.shared.global [%0], [%1], 16;" :: "r"(sm), "l"(g));
    }
    asm volatile("cp.async.commit_group;");
}

__device__ __forceinline__ void gather_rows_act(const float* __restrict__ Y,
                                                const int* __restrict__ adj,
                                                const int* __restrict__ off,
                                                const int* __restrict__ deg,
                                                const float* __restrict__ bg,
                                                float* __restrict__ Abuf,
                                                int row0, int N, int warp, int nwarps, int lane) {
    float4 bg4 = __ldg(((const float4*)bg) + lane);
    for (int row = warp; row < 128; row += nwarps) {
        int node = row0 + row;
        float4 a0 = make_float4(0.f, 0.f, 0.f, 0.f);
        float4 a1 = a0, a2 = a0, a3 = a0;
        if (node < N) {
            a0 = __ldg(((const float4*)(Y + (size_t)node * 128)) + lane);
            const int start = __ldg(off + node);
            const int d = __ldg(deg + node);
            int j = 0;
            for (; j + 4 <= d; j += 4) {
                int n0 = __ldg(adj + start + j);
                int n1 = __ldg(adj + start + j + 1);
                int n2 = __ldg(adj + start + j + 2);
                int n3 = __ldg(adj + start + j + 3);
                float4 v0 = __ldg(((const float4*)(Y + (size_t)n0 * 128)) + lane);
                float4 v1 = __ldg(((const float4*)(Y + (size_t)n1 * 128)) + lane);
                float4 v2 = __ldg(((const float4*)(Y + (size_t)n2 * 128)) + lane);
                float4 v3 = __ldg(((const float4*)(Y + (size_t)n3 * 128)) + lane);
                a0.x += v0.x; a0.y += v0.y; a0.z += v0.z; a0.w += v0.w;
                a1.x += v1.x; a1.y += v1.y; a1.z += v1.z; a1.w += v1.w;
                a2.x += v2.x; a2.y += v2.y; a2.z += v2.z; a2.w += v2.w;
                a3.x += v3.x; a3.y += v3.y; a3.z += v3.z; a3.w += v3.w;
            }
            for (; j < d; j++) {
                int n0 = __ldg(adj + start + j);
                float4 v0 = __ldg(((const float4*)(Y + (size_t)n0 * 128)) + lane);
                a0.x += v0.x; a0.y += v0.y; a0.z += v0.z; a0.w += v0.w;
            }
            a0.x = fmaxf(a0.x + a1.x + a2.x + a3.x + bg4.x, 0.f);
            a0.y = fmaxf(a0.y + a1.y + a2.y + a3.y + bg4.y, 0.f);
            a0.z = fmaxf(a0.z + a1.z + a2.z + a3.z + bg4.z, 0.f);
            a0.w = fmaxf(a0.w + a1.w + a2.w + a3.w + bg4.w, 0.f);
        }
        *(float4*)&Abuf[row * AS + lane * 4] = a0;
    }
}

__device__ __forceinline__ void gemm_from_atile(const float* __restrict__ Atile,
                                                const float* __restrict__ W,
                                                float* __restrict__ Ws,
                                                int tid, int rrow, int ccol,
                                                unsigned long long acc[8][4]) {
    stage_w(W, Ws, 0, tid);
    for (int s = 0; s < 8; s++) {
        if (s < 7) {
            stage_w(W, Ws + ((s + 1) & 1) * 2048, (s + 1) * 16, tid);
            asm volatile("cp.async.wait_group 1;");
        } else {
            asm volatile("cp.async.wait_group 0;");
        }
        CONS_BAR();
        const float* Wb = Ws + (s & 1) * 2048;
#pragma unroll
        for (int k4l = 0; k4l < 4; k4l++) {
            const int kg = s * 16 + k4l * 4;
            float4 av[8];
#pragma unroll
            for (int i = 0; i < 8; i++)
                av[i] = *(const float4*)&Atile[(rrow + i) * AS + kg];
#pragma unroll
            for (int kk = 0; kk < 4; kk++) {
                const float* wrow = Wb + (k4l * 4 + kk) * 128 + ccol;
                ulonglong2 w01 = *(const ulonglong2*)wrow;
                ulonglong2 w23 = *(const ulonglong2*)(wrow + 4);
#pragma unroll
                for (int i = 0; i < 8; i++) {
                    float a = (kk == 0) ? av[i].x : (kk == 1) ? av[i].y
                            : (kk == 2) ? av[i].z : av[i].w;
                    unsigned long long a2;
                    asm("mov.b64 %0, {%1, %1};" : "=l"(a2) : "f"(a));
                    asm("fma.rn.f32x2 %0, %1, %2, %0;" : "+l"(acc[i][0]) : "l"(a2), "l"(w01.x));
                    asm("fma.rn.f32x2 %0, %1, %2, %0;" : "+l"(acc[i][1]) : "l"(a2), "l"(w01.y));
                    asm("fma.rn.f32x2 %0, %1, %2, %0;" : "+l"(acc[i][2]) : "l"(a2), "l"(w23.x));
                    asm("fma.rn.f32x2 %0, %1, %2, %0;" : "+l"(acc[i][3]) : "l"(a2), "l"(w23.y));
                }
            }
        }
        CONS_BAR();
    }
}

__global__ __launch_bounds__(512, 1)
void fused_gg_kernel(const float* __restrict__ Y,
                     const int* __restrict__ adj, const int* __restrict__ off,
                     const int* __restrict__ deg,
                     const float* __restrict__ bg,            // gather bias (pre-relu)
                     const float* __restrict__ W, const float* __restrict__ bw,
                     float* __restrict__ OUT,
                     const int* __restrict__ batch, float* __restrict__ pool,
                     int N, int mode) {
    extern __shared__ float sm[];
    float* Abuf0 = sm;
    float* Abuf1 = sm + 128 * AS;
    float* Ws    = sm + 2 * 128 * AS;

    const int tid = threadIdx.x, wid = tid >> 5, lane = tid & 31;
    const int bid = blockIdx.x;
    const int ntiles = (N + 127) / 128;
    const int nt = (ntiles - bid + NSM - 1) / NSM;
    if (nt <= 0) return;

    const int tx = tid & 15, ty = (tid & 255) >> 4;
    const int rrow = ty * 8, ccol = tx * 8;

    // prologue: all 16 warps gather tile 0
    gather_rows_act(Y, adj, off, deg, bg, Abuf0, bid * 128, N, wid, 16, lane);
    __syncthreads();

    for (int i = 0; i < nt; i++) {
        float* Ab = (i & 1) ? Abuf1 : Abuf0;
        int row0 = (bid + i * NSM) * 128;
        if (tid < 256) {
            unsigned long long acc[8][4];
#pragma unroll
            for (int a = 0; a < 8; a++)
#pragma unroll
                for (int b = 0; b < 4; b++) acc[a][b] = 0ull;

            gemm_from_atile(Ab, W, Ws, tid, rrow, ccol, acc);

            float4 bv0 = __ldg((const float4*)(bw + ccol));
            float4 bv1 = __ldg((const float4*)(bw + ccol + 4));
            float bb[8] = {bv0.x, bv0.y, bv0.z, bv0.w, bv1.x, bv1.y, bv1.z, bv1.w};
#pragma unroll
            for (int r = 0; r < 8; r++) {
                int grow = row0 + rrow + r;
                if (grow < N) {
                    float o[8];
#pragma unroll
                    for (int j = 0; j < 4; j++) {
                        float lo, hi;
                        asm("mov.b64 {%0, %1}, %2;" : "=f"(lo), "=f"(hi) : "l"(acc[r][j]));
                        o[2 * j]     = lo + bb[2 * j];
                        o[2 * j + 1] = hi + bb[2 * j + 1];
                    }
                    if (mode == 0) {
                        *(float4*)(OUT + (size_t)grow * 128 + ccol)     = make_float4(o[0], o[1], o[2], o[3]);
                        *(float4*)(OUT + (size_t)grow * 128 + ccol + 4) = make_float4(o[4], o[5], o[6], o[7]);
                    } else {
                        int g = __ldg(batch + grow);
                        float* p = pool + (size_t)g * 128 + ccol;
                        asm volatile("red.global.add.v4.f32 [%0], {%1, %2, %3, %4};"
                                     :: "l"(p), "f"(o[0]), "f"(o[1]), "f"(o[2]), "f"(o[3]) : "memory");
                        asm volatile("red.global.add.v4.f32 [%0], {%1, %2, %3, %4};"
                                     :: "l"(p + 4), "f"(o[4]), "f"(o[5]), "f"(o[6]), "f"(o[7]) : "memory");
                    }
                }
            }
        } else {
            if (i + 1 < nt) {
                float* An = (i & 1) ? Abuf0 : Abuf1;
                gather_rows_act(Y, adj, off, deg, bg, An, (bid + (i + 1) * NSM) * 128,
                                N, wid - 8, 8, lane);
            }
        }
        __syncthreads();
    }
}

// ---------------- head: out = (sums/cnt) @ Wl + bl --------------------------
__global__ void final_kernel(const float* __restrict__ sums, const float* __restrict__ cnt,
                             const float* __restrict__ Wl, const float* __restrict__ bl,
                             float* __restrict__ out) {
    int g = blockIdx.x;
    int o = threadIdx.x;  // 64 threads
    __shared__ float p[128];
    float c = fmaxf(__ldg(cnt + g), 1.0f);
    for (int k = threadIdx.x; k < 128; k += 64)
        p[k] = __ldg(sums + g * 128 + k) / c;
    __syncthreads();
    float acc = __ldg(bl + o);
#pragma unroll 16
    for (int k = 0; k < 128; k++)
        acc += p[k] * __ldg(Wl + k * 64 + o);
    out[g * 64 + o] = acc;
}

// ---------------- launch -----------------------------------------------------
extern "C" void kernel_launch(void* const* d_in, const int* in_sizes, int n_in,
                              void* d_out, int out_size) {
    const float* x     = (const float*)d_in[0];
    const int*   ei    = (const int*)  d_in[1];
    const int*   batch = (const int*)  d_in[2];
    const float* W1a = (const float*)d_in[3];
    const float* b1a = (const float*)d_in[4];
    const float* W1b = (const float*)d_in[5];
    const float* b1b = (const float*)d_in[6];
    const float* W2a = (const float*)d_in[7];
    const float* b2a = (const float*)d_in[8];
    const float* W2b = (const float*)d_in[9];
    const float* b2b = (const float*)d_in[10];
    const float* Wl  = (const float*)d_in[11];
    const float* bl  = (const float*)d_in[12];
    float* out = (float*)d_out;

    const int N = in_sizes[0] / 128;
    const int E = in_sizes[1] / 2;
    const int* src = ei;
    const int* dst = ei + E;

    float *y, *h, *pool, *cnt;
    int *deg, *off, *cur, *adj;
    cudaGetSymbolAddress((void**)&y,    g_y);
    cudaGetSymbolAddress((void**)&h,    g_h);
    cudaGetSymbolAddress((void**)&pool, g_pool);
    cudaGetSymbolAddress((void**)&cnt,  g_cnt);
    cudaGetSymbolAddress((void**)&deg,  g_deg);
    cudaGetSymbolAddress((void**)&off,  g_off);
    cudaGetSymbolAddress((void**)&cur,  g_cur);
    cudaGetSymbolAddress((void**)&adj,  g_adj);

    cudaFuncSetAttribute(fused_gg_kernel,
                         cudaFuncAttributeMaxDynamicSharedMemorySize, SMEM_BYTES);

    const int eblocks = (E + 255) / 256;
    const int nblocks = (N + 255) / 256;
    const int gblocks = (N + 127) / 128;

    // ---- CSR build ----
    zero_kernel <<<(MAXN / 4 + 255) / 256, 256>>>((float*)deg, MAXN / 4);
    count_kernel<<<eblocks, 256>>>(dst, deg, E);
    scan_kernel <<<1, 1024>>>(deg, off, cur, N);
    fill_kernel <<<eblocks, 256>>>(src, dst, cur, adj, E);

    // ---- pool init + counts ----
    zero_kernel<<<32, 256>>>(pool, 256 * 128 / 4);
    zero_kernel<<<1,  64>>>(cnt, 64);
    cnt_kernel <<<nblocks, 256>>>(batch, cnt, N);

    // ---- layer 1: Y1 = x@W1a (no bias); h = relu(Y1+ΣY1+b1a)@W1b + b1b ----
    gemm128_kernel<<<gblocks, 256>>>(x, W1a, y, N);
    fused_gg_kernel<<<NSM, 512, SMEM_BYTES>>>(
        y, adj, off, deg, b1a, W1b, b1b, h, batch, pool, N, 0);

    // ---- layer 2: Y2 = h@W2a; pool += relu(Y2+ΣY2+b2a)@W2b + b2b ----
    gemm128_kernel<<<gblocks, 256>>>(h, W2a, y, N);
    fused_gg_kernel<<<NSM, 512, SMEM_BYTES>>>(
        y, adj, off, deg, b2a, W2b, b2b, nullptr, batch, pool, N, 1);

    // ---- head ----
    final_kernel<<<256, 64>>>(pool, cnt, Wl, bl, out);
}

// round 13
// speedup vs baseline: 1.1097x; 1.0497x over previous
#include <cuda_runtime.h>
#include <cstdint>

// ---------------- scratch (device globals) ----------------------------------
#define MAXN 50336   // >= 50000 padded to tile multiple (176*286)
#define MAXE 1048576
__device__ float g_h  [MAXN * 128];
__device__ float g_pool[256 * 128];
__device__ float g_cnt [256];
__device__ int   g_deg [MAXN];
__device__ int   g_off [MAXN];
__device__ int   g_cur [MAXN];
__device__ int   g_adj [MAXE];

// ---------------- zero -------------------------------------------------------
__global__ void zero_kernel(float* __restrict__ p, int n4) {
    int i = blockIdx.x * blockDim.x + threadIdx.x;
    if (i < n4) ((float4*)p)[i] = make_float4(0.f, 0.f, 0.f, 0.f);
}

// ---------------- CSR build --------------------------------------------------
__global__ void count_kernel(const int* __restrict__ dst, int* __restrict__ deg, int E) {
    int e = blockIdx.x * blockDim.x + threadIdx.x;
    if (e < E) atomicAdd(deg + __ldg(dst + e), 1);
}

__global__ void scan_kernel(const int* __restrict__ deg, int* __restrict__ off,
                            int* __restrict__ cur, int N) {
    __shared__ int part[1024];
    const int tid = threadIdx.x;
    const int seg = (N + 1023) / 1024;
    const int start = tid * seg;
    const int end = min(start + seg, N);
    int s = 0;
    for (int i = start; i < end; i++) s += deg[i];
    part[tid] = s;
    __syncthreads();
    int v = s;
#pragma unroll
    for (int d = 1; d < 1024; d <<= 1) {
        int t = (tid >= d) ? part[tid - d] : 0;
        __syncthreads();
        part[tid] += t;
        __syncthreads();
    }
    int run = part[tid] - v;
    for (int i = start; i < end; i++) {
        off[i] = run; cur[i] = run;
        run += deg[i];
    }
}

__global__ void fill_kernel(const int* __restrict__ src, const int* __restrict__ dst,
                            int* __restrict__ cur, int* __restrict__ adj, int E) {
    int e = blockIdx.x * blockDim.x + threadIdx.x;
    if (e < E) {
        int p = atomicAdd(cur + __ldg(dst + e), 1);
        adj[p] = __ldg(src + e);
    }
}

__global__ void cnt_kernel(const int* __restrict__ batch, float* __restrict__ cnt, int N) {
    int i = blockIdx.x * blockDim.x + threadIdx.x;
    if (i < N) atomicAdd(cnt + __ldg(batch + i), 1.0f);
}

// ---------------- persistent warp-specialized fused GIN layer ----------------
#define AS 132                 // Atile row stride (floats)
#define TROWS 176              // rows per tile: 22 row-groups x 16 col-groups
#define NSM 148
#define NCONS 352              // 11 consumer warps; 5 producer warps
#define SMEM_BYTES ((2 * TROWS * AS + 2 * 16 * 128) * 4)
#define CONS_BAR() asm volatile("bar.sync 1, 352;" ::: "memory")

__device__ __forceinline__ void stage_w(const float* __restrict__ W, float* __restrict__ Wsm,
                                        int k0, int tid) {
    for (int ch = tid; ch < 512; ch += NCONS) {
        int r = ch >> 5, c4 = ch & 31;
        const float* g = W + (size_t)(k0 + r) * 128 + c4 * 4;
        unsigned sm = (unsigned)__cvta_generic_to_shared(Wsm + r * 128 + c4 * 4);
        asm volatile("cp.async.cg.shared.global [%0], [%1], 16;" :: "r"(sm), "l"(g));
    }
    asm volatile("cp.async.commit_group;");
}

__device__ __forceinline__ void gather_rows(const float* __restrict__ X,
                                            const int* __restrict__ adj,
                                            const int* __restrict__ off,
                                            const int* __restrict__ deg,
                                            float* __restrict__ Abuf,
                                            int row0, int N, int warp, int nwarps, int lane) {
    for (int row = warp; row < TROWS; row += nwarps) {
        int node = row0 + row;
        float4 a0 = make_float4(0.f, 0.f, 0.f, 0.f);
        float4 a1 = a0, a2 = a0, a3 = a0;
        if (node < N) {
            a0 = __ldg(((const float4*)(X + (size_t)node * 128)) + lane);
            const int start = __ldg(off + node);
            const int d = __ldg(deg + node);
            int j = 0;
            for (; j + 4 <= d; j += 4) {
                int n0 = __ldg(adj + start + j);
                int n1 = __ldg(adj + start + j + 1);
                int n2 = __ldg(adj + start + j + 2);
                int n3 = __ldg(adj + start + j + 3);
                float4 v0 = __ldg(((const float4*)(X + (size_t)n0 * 128)) + lane);
                float4 v1 = __ldg(((const float4*)(X + (size_t)n1 * 128)) + lane);
                float4 v2 = __ldg(((const float4*)(X + (size_t)n2 * 128)) + lane);
                float4 v3 = __ldg(((const float4*)(X + (size_t)n3 * 128)) + lane);
                a0.x += v0.x; a0.y += v0.y; a0.z += v0.z; a0.w += v0.w;
                a1.x += v1.x; a1.y += v1.y; a1.z += v1.z; a1.w += v1.w;
                a2.x += v2.x; a2.y += v2.y; a2.z += v2.z; a2.w += v2.w;
                a3.x += v3.x; a3.y += v3.y; a3.z += v3.z; a3.w += v3.w;
            }
            for (; j < d; j++) {
                int n0 = __ldg(adj + start + j);
                float4 v0 = __ldg(((const float4*)(X + (size_t)n0 * 128)) + lane);
                a0.x += v0.x; a0.y += v0.y; a0.z += v0.z; a0.w += v0.w;
            }
            a0.x += a1.x + a2.x + a3.x;
            a0.y += a1.y + a2.y + a3.y;
            a0.z += a1.z + a2.z + a3.z;
            a0.w += a1.w + a2.w + a3.w;
        }
        *(float4*)&Abuf[row * AS + lane * 4] = a0;
    }
}

__device__ __forceinline__ void gemm_from_atile(const float* __restrict__ Atile,
                                                const float* __restrict__ W,
                                                float* __restrict__ Ws,
                                                int tid, int rrow, int ccol,
                                                unsigned long long acc[8][4]) {
    stage_w(W, Ws, 0, tid);
    for (int s = 0; s < 8; s++) {
        if (s < 7) {
            stage_w(W, Ws + ((s + 1) & 1) * 2048, (s + 1) * 16, tid);
            asm volatile("cp.async.wait_group 1;");
        } else {
            asm volatile("cp.async.wait_group 0;");
        }
        CONS_BAR();
        const float* Wb = Ws + (s & 1) * 2048;
#pragma unroll
        for (int k4l = 0; k4l < 4; k4l++) {
            const int kg = s * 16 + k4l * 4;
            float4 av[8];
#pragma unroll
            for (int i = 0; i < 8; i++)
                av[i] = *(const float4*)&Atile[(rrow + i) * AS + kg];
#pragma unroll
            for (int kk = 0; kk < 4; kk++) {
                const float* wrow = Wb + (k4l * 4 + kk) * 128 + ccol;
                ulonglong2 w01 = *(const ulonglong2*)wrow;
                ulonglong2 w23 = *(const ulonglong2*)(wrow + 4);
#pragma unroll
                for (int i = 0; i < 8; i++) {
                    float a = (kk == 0) ? av[i].x : (kk == 1) ? av[i].y
                            : (kk == 2) ? av[i].z : av[i].w;
                    unsigned long long a2;
                    asm("mov.b64 %0, {%1, %1};" : "=l"(a2) : "f"(a));
                    asm("fma.rn.f32x2 %0, %1, %2, %0;" : "+l"(acc[i][0]) : "l"(a2), "l"(w01.x));
                    asm("fma.rn.f32x2 %0, %1, %2, %0;" : "+l"(acc[i][1]) : "l"(a2), "l"(w01.y));
                    asm("fma.rn.f32x2 %0, %1, %2, %0;" : "+l"(acc[i][2]) : "l"(a2), "l"(w23.x));
                    asm("fma.rn.f32x2 %0, %1, %2, %0;" : "+l"(acc[i][3]) : "l"(a2), "l"(w23.y));
                }
            }
        }
        CONS_BAR();
    }
}

__device__ __forceinline__ void consumer_tile(float* __restrict__ Atile,
                                              float* __restrict__ Ws,
                                              const float* __restrict__ Wa, const float* __restrict__ ba,
                                              const float* __restrict__ Wb, const float* __restrict__ bbv,
                                              float* __restrict__ OUT,
                                              const int* __restrict__ batch, float* __restrict__ pool,
                                              int row0, int N, int mode,
                                              int tid, int rrow, int ccol) {
    unsigned long long acc[8][4];
#pragma unroll
    for (int i = 0; i < 8; i++)
#pragma unroll
        for (int j = 0; j < 4; j++) acc[i][j] = 0ull;

    gemm_from_atile(Atile, Wa, Ws, tid, rrow, ccol, acc);

    {   // epilogue1: relu+bias -> Atile
        float4 bv0 = __ldg((const float4*)(ba + ccol));
        float4 bv1 = __ldg((const float4*)(ba + ccol + 4));
        float bb[8] = {bv0.x, bv0.y, bv0.z, bv0.w, bv1.x, bv1.y, bv1.z, bv1.w};
#pragma unroll
        for (int i = 0; i < 8; i++) {
            float o[8];
#pragma unroll
            for (int j = 0; j < 4; j++) {
                float lo, hi;
                asm("mov.b64 {%0, %1}, %2;" : "=f"(lo), "=f"(hi) : "l"(acc[i][j]));
                o[2 * j]     = fmaxf(lo + bb[2 * j], 0.f);
                o[2 * j + 1] = fmaxf(hi + bb[2 * j + 1], 0.f);
                acc[i][j] = 0ull;
            }
            *(float4*)&Atile[(rrow + i) * AS + ccol]     = make_float4(o[0], o[1], o[2], o[3]);
            *(float4*)&Atile[(rrow + i) * AS + ccol + 4] = make_float4(o[4], o[5], o[6], o[7]);
        }
    }
    CONS_BAR();

    gemm_from_atile(Atile, Wb, Ws, tid, rrow, ccol, acc);

    {   // epilogue2
        float4 bv0 = __ldg((const float4*)(bbv + ccol));
        float4 bv1 = __ldg((const float4*)(bbv + ccol + 4));
        float bb[8] = {bv0.x, bv0.y, bv0.z, bv0.w, bv1.x, bv1.y, bv1.z, bv1.w};
#pragma unroll
        for (int i = 0; i < 8; i++) {
            int grow = row0 + rrow + i;
            if (grow < N) {
                float o[8];
#pragma unroll
                for (int j = 0; j < 4; j++) {
                    float lo, hi;
                    asm("mov.b64 {%0, %1}, %2;" : "=f"(lo), "=f"(hi) : "l"(acc[i][j]));
                    o[2 * j]     = lo + bb[2 * j];
                    o[2 * j + 1] = hi + bb[2 * j + 1];
                }
                if (mode == 0) {
                    *(float4*)(OUT + (size_t)grow * 128 + ccol)     = make_float4(o[0], o[1], o[2], o[3]);
                    *(float4*)(OUT + (size_t)grow * 128 + ccol + 4) = make_float4(o[4], o[5], o[6], o[7]);
                } else {
                    int g = __ldg(batch + grow);
                    float* p = pool + (size_t)g * 128 + ccol;
                    asm volatile("red.global.add.v4.f32 [%0], {%1, %2, %3, %4};"
                                 :: "l"(p), "f"(o[0]), "f"(o[1]), "f"(o[2]), "f"(o[3]) : "memory");
                    asm volatile("red.global.add.v4.f32 [%0], {%1, %2, %3, %4};"
                                 :: "l"(p + 4), "f"(o[4]), "f"(o[5]), "f"(o[6]), "f"(o[7]) : "memory");
                }
            }
        }
    }
}

__global__ __launch_bounds__(512, 1)
void fused_layer_kernel(const float* __restrict__ X,
                        const int* __restrict__ adj, const int* __restrict__ off,
                        const int* __restrict__ deg,
                        const float* __restrict__ Wa, const float* __restrict__ ba,
                        const float* __restrict__ Wb, const float* __restrict__ bbv,
                        float* __restrict__ OUT,
                        const int* __restrict__ batch, float* __restrict__ pool,
                        int N, int mode) {
    extern __shared__ float sm[];
    float* Abuf0 = sm;
    float* Abuf1 = sm + TROWS * AS;
    float* Ws    = sm + 2 * TROWS * AS;

    const int tid = threadIdx.x, wid = tid >> 5, lane = tid & 31;
    const int bid = blockIdx.x;
    const int ntiles = (N + TROWS - 1) / TROWS;   // 285 for N=50000
    const int nt = (ntiles - bid + NSM - 1) / NSM;
    if (nt <= 0) return;

    // consumer geometry (tid 0..351): 22 row-groups x 16 col-groups
    const int tx = tid & 15, ty = tid >> 4;
    const int rrow = ty * 8, ccol = tx * 8;

    // prologue: all 16 warps gather tile 0
    gather_rows(X, adj, off, deg, Abuf0, bid * TROWS, N, wid, 16, lane);
    __syncthreads();

    for (int i = 0; i < nt; i++) {
        float* Ab = (i & 1) ? Abuf1 : Abuf0;
        int row0 = (bid + i * NSM) * TROWS;
        if (tid < NCONS) {
            consumer_tile(Ab, Ws, Wa, ba, Wb, bbv, OUT, batch, pool,
                          row0, N, mode, tid, rrow, ccol);
        } else {
            if (i + 1 < nt) {
                float* An = (i & 1) ? Abuf0 : Abuf1;
                gather_rows(X, adj, off, deg, An, (bid + (i + 1) * NSM) * TROWS,
                            N, wid - 11, 5, lane);
            }
        }
        __syncthreads();
    }
}

// ---------------- head: out = (sums/cnt) @ Wl + bl --------------------------
__global__ void final_kernel(const float* __restrict__ sums, const float* __restrict__ cnt,
                             const float* __restrict__ Wl, const float* __restrict__ bl,
                             float* __restrict__ out) {
    int g = blockIdx.x;
    int o = threadIdx.x;  // 64 threads
    __shared__ float p[128];
    float c = fmaxf(__ldg(cnt + g), 1.0f);
    for (int k = threadIdx.x; k < 128; k += 64)
        p[k] = __ldg(sums + g * 128 + k) / c;
    __syncthreads();
    float acc = __ldg(bl + o);
#pragma unroll 16
    for (int k = 0; k < 128; k++)
        acc += p[k] * __ldg(Wl + k * 64 + o);
    out[g * 64 + o] = acc;
}

// ---------------- launch -----------------------------------------------------
extern "C" void kernel_launch(void* const* d_in, const int* in_sizes, int n_in,
                              void* d_out, int out_size) {
    const float* x     = (const float*)d_in[0];
    const int*   ei    = (const int*)  d_in[1];
    const int*   batch = (const int*)  d_in[2];
    const float* W1a = (const float*)d_in[3];
    const float* b1a = (const float*)d_in[4];
    const float* W1b = (const float*)d_in[5];
    const float* b1b = (const float*)d_in[6];
    const float* W2a = (const float*)d_in[7];
    const float* b2a = (const float*)d_in[8];
    const float* W2b = (const float*)d_in[9];
    const float* b2b = (const float*)d_in[10];
    const float* Wl  = (const float*)d_in[11];
    const float* bl  = (const float*)d_in[12];
    float* out = (float*)d_out;

    const int N = in_sizes[0] / 128;
    const int E = in_sizes[1] / 2;
    const int* src = ei;
    const int* dst = ei + E;

    float *h, *pool, *cnt;
    int *deg, *off, *cur, *adj;
    cudaGetSymbolAddress((void**)&h,    g_h);
    cudaGetSymbolAddress((void**)&pool, g_pool);
    cudaGetSymbolAddress((void**)&cnt,  g_cnt);
    cudaGetSymbolAddress((void**)&deg,  g_deg);
    cudaGetSymbolAddress((void**)&off,  g_off);
    cudaGetSymbolAddress((void**)&cur,  g_cur);
    cudaGetSymbolAddress((void**)&adj,  g_adj);

    cudaFuncSetAttribute(fused_layer_kernel,
                         cudaFuncAttributeMaxDynamicSharedMemorySize, SMEM_BYTES);

    const int eblocks = (E + 255) / 256;
    const int nblocks = (N + 255) / 256;

    // ---- CSR build (once per launch) ----
    zero_kernel <<<(MAXN / 4 + 255) / 256, 256>>>((float*)deg, MAXN / 4);
    count_kernel<<<eblocks, 256>>>(dst, deg, E);
    scan_kernel <<<1, 1024>>>(deg, off, cur, N);
    fill_kernel <<<eblocks, 256>>>(src, dst, cur, adj, E);

    // ---- pool init + counts ----
    zero_kernel<<<32, 256>>>(pool, 256 * 128 / 4);
    zero_kernel<<<1,  64>>>(cnt, 64);
    cnt_kernel <<<nblocks, 256>>>(batch, cnt, N);

    // ---- layer 1: h = MLP1(x + gather) ----
    fused_layer_kernel<<<NSM, 512, SMEM_BYTES>>>(
        x, adj, off, deg, W1a, b1a, W1b, b1b, h, batch, pool, N, 0);

    // ---- layer 2: pool += MLP2(h + gather), fused ----
    fused_layer_kernel<<<NSM, 512, SMEM_BYTES>>>(
        h, adj, off, deg, W2a, b2a, W2b, b2b, nullptr, batch, pool, N, 1);

    // ---- head ----
    final_kernel<<<256, 64>>>(pool, cnt, Wl, bl, out);
}

// round 14
// speedup vs baseline: 1.1732x; 1.0571x over previous
#include <cuda_runtime.h>
#include <cstdint>

// ---------------- scratch (device globals) ----------------------------------
#define MAXN 50176   // padded 50000
#define MAXE 1048576
__device__ float g_h  [MAXN * 128];
__device__ float g_pool[256 * 128 + 256];   // [0,32768) pool sums, [32768,33024) cnt
__device__ int   g_deg [MAXN + 1];
__device__ int   g_off [MAXN + 1];
__device__ int   g_cur [MAXN];
__device__ int   g_adj [MAXE];

// ---------------- zero -------------------------------------------------------
__global__ void zero_kernel(float* __restrict__ p, int n4) {
    int i = blockIdx.x * blockDim.x + threadIdx.x;
    if (i < n4) ((float4*)p)[i] = make_float4(0.f, 0.f, 0.f, 0.f);
}

// ---------------- CSR build --------------------------------------------------
// deg is zero on entry: zero-init at load, re-zeroed by fill_kernel each call.
__global__ void count_kernel(const int* __restrict__ dst, int* __restrict__ deg, int E) {
    int e = blockIdx.x * blockDim.x + threadIdx.x;
    if (e < E) atomicAdd(deg + __ldg(dst + e), 1);
}

__global__ void scan_kernel(const int* __restrict__ deg, int* __restrict__ off,
                            int* __restrict__ cur, int N) {
    __shared__ int part[1024];
    const int tid = threadIdx.x;
    const int seg = (N + 1023) / 1024;
    const int start = tid * seg;
    const int end = min(start + seg, N);
    int s = 0;
    for (int i = start; i < end; i++) s += deg[i];
    part[tid] = s;
    __syncthreads();
    int v = s;
#pragma unroll
    for (int d = 1; d < 1024; d <<= 1) {
        int t = (tid >= d) ? part[tid - d] : 0;
        __syncthreads();
        part[tid] += t;
        __syncthreads();
    }
    int run = part[tid] - v;
    for (int i = start; i < end; i++) {
        off[i] = run; cur[i] = run;
        run += deg[i];
    }
    if (end == N) off[N] = run;   // total E (all trailing threads write same value)
}

__global__ void fill_kernel(const int* __restrict__ src, const int* __restrict__ dst,
                            int* __restrict__ cur, int* __restrict__ adj,
                            int* __restrict__ deg, int E) {
    int e = blockIdx.x * blockDim.x + threadIdx.x;
    if (e < E) {
        int p = atomicAdd(cur + __ldg(dst + e), 1);
        adj[p] = __ldg(src + e);
    }
    if (e <= MAXN) deg[e] = 0;   // reset for next replay (deg unused after scan)
}

__global__ void cnt_kernel(const int* __restrict__ batch, float* __restrict__ cnt, int N) {
    int i = blockIdx.x * blockDim.x + threadIdx.x;
    if (i < N) atomicAdd(cnt + __ldg(batch + i), 1.0f);
}

// ---------------- persistent warp-specialized fused GIN layer ----------------
#define AS 132                 // Atile row stride (floats)
#define TROWS 128
#define NSM 148
#define NCONS 256              // 8 consumer warps; 8 producer warps
#define TK 32
#define SMEM_BYTES ((2 * TROWS * AS + 2 * TK * 128) * 4)
#define CONS_BAR() asm volatile("bar.sync 1, 256;" ::: "memory")

__device__ __forceinline__ void stage_w(const float* __restrict__ W, float* __restrict__ Wsm,
                                        int k0, int tid) {
#pragma unroll
    for (int t = 0; t < 4; t++) {
        int ch = tid + t * NCONS;                // 0..1023: 32 rows x 32 float4
        int r = ch >> 5, c4 = ch & 31;
        const float* g = W + (size_t)(k0 + r) * 128 + c4 * 4;
        unsigned sm = (unsigned)__cvta_generic_to_shared(Wsm + r * 128 + c4 * 4);
        asm volatile("cp.async.cg.shared.global [%0], [%1], 16;" :: "r"(sm), "l"(g));
    }
    asm volatile("cp.async.commit_group;");
}

// pipelined gather: Abuf[row] = X[node] + sum_{j in adj(node)} X[j]
__device__ __forceinline__ void gather_rows(const float* __restrict__ X,
                                            const int* __restrict__ adj,
                                            const int* __restrict__ off,
                                            float* __restrict__ Abuf,
                                            int row0, int N, int warp, int nwarps, int lane) {
    for (int row = warp; row < TROWS; row += nwarps) {
        int node = row0 + row;
        float4 a0 = make_float4(0.f, 0.f, 0.f, 0.f);
        float4 a1 = a0, a2 = a0, a3 = a0;
        if (node < N) {
            a0 = __ldg(((const float4*)(X + (size_t)node * 128)) + lane);
            const int start = __ldg(off + node);
            const int d = __ldg(off + node + 1) - start;
            const int* ap = adj + start;
            int j = 0;
            int n0 = 0, n1 = 0, n2 = 0, n3 = 0;
            if (d >= 4) {   // preload first quad of indices
                n0 = __ldg(ap + 0); n1 = __ldg(ap + 1);
                n2 = __ldg(ap + 2); n3 = __ldg(ap + 3);
            }
            for (; j + 8 <= d; j += 4) {
                float4 v0 = __ldg(((const float4*)(X + (size_t)n0 * 128)) + lane);
                float4 v1 = __ldg(((const float4*)(X + (size_t)n1 * 128)) + lane);
                float4 v2 = __ldg(((const float4*)(X + (size_t)n2 * 128)) + lane);
                float4 v3 = __ldg(((const float4*)(X + (size_t)n3 * 128)) + lane);
                n0 = __ldg(ap + j + 4); n1 = __ldg(ap + j + 5);   // prefetch next quad
                n2 = __ldg(ap + j + 6); n3 = __ldg(ap + j + 7);   // overlaps v-loads
                a0.x += v0.x; a0.y += v0.y; a0.z += v0.z; a0.w += v0.w;
                a1.x += v1.x; a1.y += v1.y; a1.z += v1.z; a1.w += v1.w;
                a2.x += v2.x; a2.y += v2.y; a2.z += v2.z; a2.w += v2.w;
                a3.x += v3.x; a3.y += v3.y; a3.z += v3.z; a3.w += v3.w;
            }
            if (j + 4 <= d) {   // last full quad (indices already resident)
                float4 v0 = __ldg(((const float4*)(X + (size_t)n0 * 128)) + lane);
                float4 v1 = __ldg(((const float4*)(X + (size_t)n1 * 128)) + lane);
                float4 v2 = __ldg(((const float4*)(X + (size_t)n2 * 128)) + lane);
                float4 v3 = __ldg(((const float4*)(X + (size_t)n3 * 128)) + lane);
                a0.x += v0.x; a0.y += v0.y; a0.z += v0.z; a0.w += v0.w;
                a1.x += v1.x; a1.y += v1.y; a1.z += v1.z; a1.w += v1.w;
                a2.x += v2.x; a2.y += v2.y; a2.z += v2.z; a2.w += v2.w;
                a3.x += v3.x; a3.y += v3.y; a3.z += v3.z; a3.w += v3.w;
                j += 4;
            }
            for (; j < d; j++) {
                int n = __ldg(ap + j);
                float4 v = __ldg(((const float4*)(X + (size_t)n * 128)) + lane);
                a0.x += v.x; a0.y += v.y; a0.z += v.z; a0.w += v.w;
            }
            a0.x += a1.x + a2.x + a3.x;
            a0.y += a1.y + a2.y + a3.y;
            a0.z += a1.z + a2.z + a3.z;
            a0.w += a1.w + a2.w + a3.w;
        }
        *(float4*)&Abuf[row * AS + lane * 4] = a0;
    }
}

__device__ __forceinline__ void gemm_from_atile(const float* __restrict__ Atile,
                                                const float* __restrict__ W,
                                                float* __restrict__ Ws,
                                                int tid, int rrow, int ccol,
                                                unsigned long long acc[8][4]) {
    stage_w(W, Ws, 0, tid);
    for (int s = 0; s < 128 / TK; s++) {
        if (s < 128 / TK - 1) {
            stage_w(W, Ws + ((s + 1) & 1) * (TK * 128), (s + 1) * TK, tid);
            asm volatile("cp.async.wait_group 1;");
        } else {
            asm volatile("cp.async.wait_group 0;");
        }
        CONS_BAR();
        const float* Wb = Ws + (s & 1) * (TK * 128);
#pragma unroll
        for (int k4l = 0; k4l < TK / 4; k4l++) {
            const int kg = s * TK + k4l * 4;
            float4 av[8];
#pragma unroll
            for (int i = 0; i < 8; i++)
                av[i] = *(const float4*)&Atile[(rrow + i) * AS + kg];
#pragma unroll
            for (int kk = 0; kk < 4; kk++) {
                const float* wrow = Wb + (k4l * 4 + kk) * 128 + ccol;
                ulonglong2 w01 = *(const ulonglong2*)wrow;
                ulonglong2 w23 = *(const ulonglong2*)(wrow + 4);
#pragma unroll
                for (int i = 0; i < 8; i++) {
                    float a = (kk == 0) ? av[i].x : (kk == 1) ? av[i].y
                            : (kk == 2) ? av[i].z : av[i].w;
                    unsigned long long a2;
                    asm("mov.b64 %0, {%1, %1};" : "=l"(a2) : "f"(a));
                    asm("fma.rn.f32x2 %0, %1, %2, %0;" : "+l"(acc[i][0]) : "l"(a2), "l"(w01.x));
                    asm("fma.rn.f32x2 %0, %1, %2, %0;" : "+l"(acc[i][1]) : "l"(a2), "l"(w01.y));
                    asm("fma.rn.f32x2 %0, %1, %2, %0;" : "+l"(acc[i][2]) : "l"(a2), "l"(w23.x));
                    asm("fma.rn.f32x2 %0, %1, %2, %0;" : "+l"(acc[i][3]) : "l"(a2), "l"(w23.y));
                }
            }
        }
        CONS_BAR();
    }
}

__device__ __forceinline__ void consumer_tile(float* __restrict__ Atile,
                                              float* __restrict__ Ws,
                                              const float* __restrict__ Wa, const float* __restrict__ ba,
                                              const float* __restrict__ Wb, const float* __restrict__ bbv,
                                              float* __restrict__ OUT,
                                              const int* __restrict__ batch, float* __restrict__ pool,
                                              int row0, int N, int mode,
                                              int tid, int rrow, int ccol) {
    unsigned long long acc[8][4];
#pragma unroll
    for (int i = 0; i < 8; i++)
#pragma unroll
        for (int j = 0; j < 4; j++) acc[i][j] = 0ull;

    gemm_from_atile(Atile, Wa, Ws, tid, rrow, ccol, acc);

    {   // epilogue1: relu+bias -> Atile
        float4 bv0 = __ldg((const float4*)(ba + ccol));
        float4 bv1 = __ldg((const float4*)(ba + ccol + 4));
        float bb[8] = {bv0.x, bv0.y, bv0.z, bv0.w, bv1.x, bv1.y, bv1.z, bv1.w};
#pragma unroll
        for (int i = 0; i < 8; i++) {
            float o[8];
#pragma unroll
            for (int j = 0; j < 4; j++) {
                float lo, hi;
                asm("mov.b64 {%0, %1}, %2;" : "=f"(lo), "=f"(hi) : "l"(acc[i][j]));
                o[2 * j]     = fmaxf(lo + bb[2 * j], 0.f);
                o[2 * j + 1] = fmaxf(hi + bb[2 * j + 1], 0.f);
                acc[i][j] = 0ull;
            }
            *(float4*)&Atile[(rrow + i) * AS + ccol]     = make_float4(o[0], o[1], o[2], o[3]);
            *(float4*)&Atile[(rrow + i) * AS + ccol + 4] = make_float4(o[4], o[5], o[6], o[7]);
        }
    }
    CONS_BAR();

    gemm_from_atile(Atile, Wb, Ws, tid, rrow, ccol, acc);

    {   // epilogue2
        float4 bv0 = __ldg((const float4*)(bbv + ccol));
        float4 bv1 = __ldg((const float4*)(bbv + ccol + 4));
        float bb[8] = {bv0.x, bv0.y, bv0.z, bv0.w, bv1.x, bv1.y, bv1.z, bv1.w};
#pragma unroll
        for (int i = 0; i < 8; i++) {
            int grow = row0 + rrow + i;
            if (grow < N) {
                float o[8];
#pragma unroll
                for (int j = 0; j < 4; j++) {
                    float lo, hi;
                    asm("mov.b64 {%0, %1}, %2;" : "=f"(lo), "=f"(hi) : "l"(acc[i][j]));
                    o[2 * j]     = lo + bb[2 * j];
                    o[2 * j + 1] = hi + bb[2 * j + 1];
                }
                if (mode == 0) {
                    *(float4*)(OUT + (size_t)grow * 128 + ccol)     = make_float4(o[0], o[1], o[2], o[3]);
                    *(float4*)(OUT + (size_t)grow * 128 + ccol + 4) = make_float4(o[4], o[5], o[6], o[7]);
                } else {
                    int g = __ldg(batch + grow);
                    float* p = pool + (size_t)g * 128 + ccol;
                    asm volatile("red.global.add.v4.f32 [%0], {%1, %2, %3, %4};"
                                 :: "l"(p), "f"(o[0]), "f"(o[1]), "f"(o[2]), "f"(o[3]) : "memory");
                    asm volatile("red.global.add.v4.f32 [%0], {%1, %2, %3, %4};"
                                 :: "l"(p + 4), "f"(o[4]), "f"(o[5]), "f"(o[6]), "f"(o[7]) : "memory");
                }
            }
        }
    }
}

__global__ __launch_bounds__(512, 1)
void fused_layer_kernel(const float* __restrict__ X,
                        const int* __restrict__ adj, const int* __restrict__ off,
                        const float* __restrict__ Wa, const float* __restrict__ ba,
                        const float* __restrict__ Wb, const float* __restrict__ bbv,
                        float* __restrict__ OUT,
                        const int* __restrict__ batch, float* __restrict__ pool,
                        int N, int mode) {
    extern __shared__ float sm[];
    float* Abuf0 = sm;
    float* Abuf1 = sm + TROWS * AS;
    float* Ws    = sm + 2 * TROWS * AS;

    const int tid = threadIdx.x, wid = tid >> 5, lane = tid & 31;
    const int bid = blockIdx.x;
    const int ntiles = (N + TROWS - 1) / TROWS;
    const int nt = (ntiles - bid + NSM - 1) / NSM;
    if (nt <= 0) return;

    const int tx = tid & 15, ty = (tid & 255) >> 4;
    const int rrow = ty * 8, ccol = tx * 8;

    // prologue: all 16 warps gather tile 0
    gather_rows(X, adj, off, Abuf0, bid * TROWS, N, wid, 16, lane);
    __syncthreads();

    for (int i = 0; i < nt; i++) {
        float* Ab = (i & 1) ? Abuf1 : Abuf0;
        int row0 = (bid + i * NSM) * TROWS;
        if (tid < NCONS) {
            consumer_tile(Ab, Ws, Wa, ba, Wb, bbv, OUT, batch, pool,
                          row0, N, mode, tid, rrow, ccol);
        } else {
            if (i + 1 < nt) {
                float* An = (i & 1) ? Abuf0 : Abuf1;
                gather_rows(X, adj, off, An, (bid + (i + 1) * NSM) * TROWS,
                            N, wid - 8, 8, lane);
            }
        }
        __syncthreads();
    }
}

// ---------------- head: out = (sums/cnt) @ Wl + bl --------------------------
__global__ void final_kernel(const float* __restrict__ sums, const float* __restrict__ cnt,
                             const float* __restrict__ Wl, const float* __restrict__ bl,
                             float* __restrict__ out) {
    int g = blockIdx.x;
    int o = threadIdx.x;  // 64 threads
    __shared__ float p[128];
    float c = fmaxf(__ldg(cnt + g), 1.0f);
    for (int k = threadIdx.x; k < 128; k += 64)
        p[k] = __ldg(sums + g * 128 + k) / c;
    __syncthreads();
    float acc = __ldg(bl + o);
#pragma unroll 16
    for (int k = 0; k < 128; k++)
        acc += p[k] * __ldg(Wl + k * 64 + o);
    out[g * 64 + o] = acc;
}

// ---------------- launch -----------------------------------------------------
extern "C" void kernel_launch(void* const* d_in, const int* in_sizes, int n_in,
                              void* d_out, int out_size) {
    const float* x     = (const float*)d_in[0];
    const int*   ei    = (const int*)  d_in[1];
    const int*   batch = (const int*)  d_in[2];
    const float* W1a = (const float*)d_in[3];
    const float* b1a = (const float*)d_in[4];
    const float* W1b = (const float*)d_in[5];
    const float* b1b = (const float*)d_in[6];
    const float* W2a = (const float*)d_in[7];
    const float* b2a = (const float*)d_in[8];
    const float* W2b = (const float*)d_in[9];
    const float* b2b = (const float*)d_in[10];
    const float* Wl  = (const float*)d_in[11];
    const float* bl  = (const float*)d_in[12];
    float* out = (float*)d_out;

    const int N = in_sizes[0] / 128;
    const int E = in_sizes[1] / 2;
    const int* src = ei;
    const int* dst = ei + E;

    float *h, *pool;
    int *deg, *off, *cur, *adj;
    cudaGetSymbolAddress((void**)&h,    g_h);
    cudaGetSymbolAddress((void**)&pool, g_pool);
    cudaGetSymbolAddress((void**)&deg,  g_deg);
    cudaGetSymbolAddress((void**)&off,  g_off);
    cudaGetSymbolAddress((void**)&cur,  g_cur);
    cudaGetSymbolAddress((void**)&adj,  g_adj);
    float* cnt = pool + 256 * 128;

    cudaFuncSetAttribute(fused_layer_kernel,
                         cudaFuncAttributeMaxDynamicSharedMemorySize, SMEM_BYTES);

    const int eblocks = (E + 255) / 256;
    const int nblocks = (N + 255) / 256;

    // ---- CSR build (deg zero at entry: zero-init / re-zeroed by fill) ----
    count_kernel<<<eblocks, 256>>>(dst, deg, E);              // #1
    scan_kernel <<<1, 1024>>>(deg, off, cur, N);              // #2
    fill_kernel <<<eblocks, 256>>>(src, dst, cur, adj, deg, E); // #3

    // ---- layer 1 (launch #4 — ncu capture target): h = MLP1(x + gather) ----
    fused_layer_kernel<<<NSM, 512, SMEM_BYTES>>>(
        x, adj, off, W1a, b1a, W1b, b1b, h, batch, pool, N, 0);

    // ---- pool/cnt init + counts (needed only by layer 2 / head) ----
    zero_kernel<<<33, 256>>>(pool, (256 * 128 + 256) / 4);    // #5
    cnt_kernel <<<nblocks, 256>>>(batch, cnt, N);             // #6

    // ---- layer 2: pool += MLP2(h + gather), fused ----
    fused_layer_kernel<<<NSM, 512, SMEM_BYTES>>>(
        h, adj, off, W2a, b2a, W2b, b2b, nullptr, batch, pool, N, 1);

    // ---- head ----
    final_kernel<<<256, 64>>>(pool, cnt, Wl, bl, out);
}